// round 11
// baseline (speedup 1.0000x reference)
#include <cuda_runtime.h>
#include <cstdint>

#define HDIM 2048
#define NTOK 8192          // B*S
#define NTHREADS 512
#define NCTAS 456          // 152 SMs * 3 resident CTAs
#define EPSV 1e-6f

struct Smem {
    float q[4][HDIM];        // fused router weights w*rw[n]  (32 KB)
    float xbuf[2][2][HDIM];  // [parity][{x0,act}][h] cp.async stage (32 KB)
    float red[2][16][10];    // ping-pong partial sums
    float coef[2][20];       // ping-pong c[16] + cc[4]
    float pw[64];
    float cw[16];
};

__device__ __forceinline__ float4 ldcs4(const float* p) {
    float4 v;
    asm volatile("ld.global.cs.v4.f32 {%0,%1,%2,%3}, [%4];"
                 : "=f"(v.x), "=f"(v.y), "=f"(v.z), "=f"(v.w) : "l"(p));
    return v;
}
__device__ __forceinline__ void stcs4(float* p, float4 v) {
    asm volatile("st.global.cs.v4.f32 [%0], {%1,%2,%3,%4};"
                 :: "l"(p), "f"(v.x), "f"(v.y), "f"(v.z), "f"(v.w));
}
__device__ __forceinline__ void cp16(uint32_t saddr, const void* g) {
    asm volatile("cp.async.cg.shared.global [%0], [%1], 16;" :: "r"(saddr), "l"(g));
}
__device__ __forceinline__ float tanh_fast(float x) {
    float y; asm("tanh.approx.f32 %0, %1;" : "=f"(y) : "f"(x)); return y;
}
__device__ __forceinline__ float dot4(float4 a, float4 b) {
    return a.x*b.x + a.y*b.y + a.z*b.z + a.w*b.w;
}

__global__ __launch_bounds__(NTHREADS, 3)
void altup_v7_kernel(const float* __restrict__ hs,     // [4, NTOK, H]
                     const float* __restrict__ act,    // [NTOK, H]
                     const float* __restrict__ w,      // [H]
                     const float* __restrict__ rw,     // [4, H]
                     const float* __restrict__ pw,     // [16, 4]
                     const float* __restrict__ cw,     // [4, 4]
                     const float* __restrict__ oscale, // [H]
                     float* __restrict__ out)          // [4, NTOK, H]
{
    extern __shared__ char smem_raw[];
    Smem* S = (Smem*)smem_raw;

    const int tid = threadIdx.x;
    const int h4  = tid * 4;
    const int warp = tid >> 5, lane = tid & 31;
    const float inv_h = 1.0f / (float)HDIM;

    // ---- one-time staging: q = w * rw ----
    #pragma unroll
    for (int r = 0; r < 4; r++) {
        float4 wv = __ldg((const float4*)(w + h4));
        float4 rv = __ldg((const float4*)(rw + r*HDIM + h4));
        *(float4*)&S->q[r][h4] = make_float4(wv.x*rv.x, wv.y*rv.y, wv.z*rv.z, wv.w*rv.w);
    }
    if (tid < 64) S->pw[tid] = pw[tid];
    if (tid < 16) S->cw[tid] = cw[tid];
    const float4 sv = __ldg((const float4*)(oscale + h4));

    // per-thread smem byte addresses of its own 16B slot in each stage row
    const uint32_t xb00 = (uint32_t)__cvta_generic_to_shared(&S->xbuf[0][0][h4]);
    const uint32_t xb01 = (uint32_t)__cvta_generic_to_shared(&S->xbuf[0][1][h4]);
    const uint32_t xb10 = (uint32_t)__cvta_generic_to_shared(&S->xbuf[1][0][h4]);
    const uint32_t xb11 = (uint32_t)__cvta_generic_to_shared(&S->xbuf[1][1][h4]);

    // ---- prologue: prefetch token t0 streams x0/act ----
    {
        int t0 = blockIdx.x;
        cp16(xb00, hs  + (size_t)t0 * HDIM + h4);
        cp16(xb01, act + (size_t)t0 * HDIM + h4);
        asm volatile("cp.async.commit_group;" ::: "memory");
    }
    __syncthreads();   // q/pw/cw staging visible

    int par = 0;
    for (int t = blockIdx.x; t < NTOK; t += NCTAS, par ^= 1) {
        // ---- wait for this token's staged x0/act (issued last iteration) ----
        asm volatile("cp.async.wait_group 0;" ::: "memory");
        float4 x0 = par ? *(const float4*)&S->xbuf[1][0][h4]
                        : *(const float4*)&S->xbuf[0][0][h4];
        float4 av = par ? *(const float4*)&S->xbuf[1][1][h4]
                        : *(const float4*)&S->xbuf[0][1][h4];

        // ---- issue next token's prefetch into the other buffer ----
        {
            int tn = t + NCTAS;
            if (tn < NTOK) {
                cp16(par ? xb00 : xb10, hs  + (size_t)tn * HDIM + h4);
                cp16(par ? xb01 : xb11, act + (size_t)tn * HDIM + h4);
            }
            asm volatile("cp.async.commit_group;" ::: "memory");
        }

        // ---- dots against smem-resident fused weights ----
        float p[10];
        {
            float4 q0 = *(const float4*)&S->q[0][h4];
            float4 q1 = *(const float4*)&S->q[1][h4];
            p[0] = dot4(x0, x0);
            p[1] = dot4(x0, q0);  p[2] = dot4(x0, q1);
            p[5] = dot4(av, av);
            p[6] = dot4(av, q0);  p[7] = dot4(av, q1);
        }
        {
            float4 q2 = *(const float4*)&S->q[2][h4];
            float4 q3 = *(const float4*)&S->q[3][h4];
            p[3] = dot4(x0, q2);  p[4] = dot4(x0, q3);
            p[8] = dot4(av, q2);  p[9] = dot4(av, q3);
        }

        // ---- prefetch phase-2 streams before the reduce ----
        float4 x1 = ldcs4(hs + ((size_t)1*NTOK + t)*HDIM + h4);
        float4 x2 = ldcs4(hs + ((size_t)2*NTOK + t)*HDIM + h4);
        float4 x3 = ldcs4(hs + ((size_t)3*NTOK + t)*HDIM + h4);

        // ---- block reduce ----
        #pragma unroll
        for (int k = 0; k < 10; k++) {
            #pragma unroll
            for (int o = 16; o > 0; o >>= 1)
                p[k] += __shfl_xor_sync(0xffffffffu, p[k], o);
        }
        if (lane == 0) {
            #pragma unroll
            for (int k = 0; k < 10; k++) S->red[par][warp][k] = p[k];
        }
        __syncthreads();

        // ---- warp 0: finalize sums + all coefficient math ----
        if (warp == 0) {
            float f = 0.f;
            if (lane < 10) {
                #pragma unroll
                for (int wi = 0; wi < 16; wi++) f += S->red[par][wi][lane];
            }
            float fin[10];
            #pragma unroll
            for (int k = 0; k < 10; k++)
                fin[k] = __shfl_sync(0xffffffffu, f, k);

            float g0 = rsqrtf(fin[0] * inv_h + EPSV) * inv_h;
            float g1 = rsqrtf(fin[5] * inv_h + EPSV) * inv_h;

            if (lane < 16) {
                float s = 0.f;
                #pragma unroll
                for (int n = 0; n < 4; n++)
                    s = fmaf(tanh_fast(fin[1 + n] * g0), S->pw[lane*4 + n], s);
                S->coef[par][lane] = s;
            } else if (lane < 20) {
                int n = lane - 16;
                float s = 1.0f;
                #pragma unroll
                for (int k = 0; k < 4; k++)
                    s = fmaf(tanh_fast(fin[6 + k] * g1), S->cw[n*4 + k], s);
                S->coef[par][16 + n] = s;
            }
        }
        __syncthreads();

        // ---- phase 2: elementwise combine ----
        const float* coef = S->coef[par];
        float xc[4][4];
        xc[0][0]=x0.x; xc[0][1]=x0.y; xc[0][2]=x0.z; xc[0][3]=x0.w;
        xc[1][0]=x1.x; xc[1][1]=x1.y; xc[1][2]=x1.z; xc[1][3]=x1.w;
        xc[2][0]=x2.x; xc[2][1]=x2.y; xc[2][2]=x2.z; xc[2][3]=x2.w;
        xc[3][0]=x3.x; xc[3][1]=x3.y; xc[3][2]=x3.z; xc[3][3]=x3.w;
        const float ac[4] = {av.x, av.y, av.z, av.w};
        const float sc[4] = {sv.x, sv.y, sv.z, sv.w};

        float pr0[4];
        {
            const float c0 = coef[0], c1 = coef[1], c2 = coef[2], c3 = coef[3];
            #pragma unroll
            for (int comp = 0; comp < 4; comp++) {
                float s = xc[0][comp];
                s = fmaf(c0, xc[0][comp], s);
                s = fmaf(c1, xc[1][comp], s);
                s = fmaf(c2, xc[2][comp], s);
                s = fmaf(c3, xc[3][comp], s);
                pr0[comp] = s;
            }
        }
        float innov[4];
        #pragma unroll
        for (int comp = 0; comp < 4; comp++) innov[comp] = ac[comp] - pr0[comp];

        {
            const float cc0 = coef[16];
            float4 o4;
            o4.x = (pr0[0] + innov[0]*cc0) * sc[0];
            o4.y = (pr0[1] + innov[1]*cc0) * sc[1];
            o4.z = (pr0[2] + innov[2]*cc0) * sc[2];
            o4.w = (pr0[3] + innov[3]*cc0) * sc[3];
            stcs4(out + ((size_t)t)*HDIM + h4, o4);
        }
        #pragma unroll
        for (int j = 1; j < 4; j++) {
            const float c0 = coef[j*4+0], c1 = coef[j*4+1],
                        c2 = coef[j*4+2], c3 = coef[j*4+3];
            const float ccj = coef[16 + j];
            float4 o4;
            float* op = &o4.x;
            #pragma unroll
            for (int comp = 0; comp < 4; comp++) {
                float s = xc[j][comp];
                s = fmaf(c0, xc[0][comp], s);
                s = fmaf(c1, xc[1][comp], s);
                s = fmaf(c2, xc[2][comp], s);
                s = fmaf(c3, xc[3][comp], s);
                op[comp] = (s + innov[comp]*ccj) * sc[comp];
            }
            stcs4(out + ((size_t)j*NTOK + t)*HDIM + h4, o4);
        }
        // no trailing barrier: red/coef ping-pong; same-parity reuse is
        // separated by the two barriers of the intervening iteration.
    }
}

extern "C" void kernel_launch(void* const* d_in, const int* in_sizes, int n_in,
                              void* d_out, int out_size)
{
    const float* hs     = (const float*)d_in[0];
    const float* act    = (const float*)d_in[1];
    const float* w      = (const float*)d_in[2];
    const float* rw     = (const float*)d_in[3];
    const float* pw     = (const float*)d_in[4];
    const float* cw     = (const float*)d_in[5];
    const float* oscale = (const float*)d_in[6];
    float* out = (float*)d_out;

    static int attr_done = 0;
    if (!attr_done) {
        cudaFuncSetAttribute(altup_v7_kernel,
                             cudaFuncAttributeMaxDynamicSharedMemorySize,
                             (int)sizeof(Smem));
        attr_done = 1;
    }
    altup_v7_kernel<<<NCTAS, NTHREADS, sizeof(Smem)>>>(hs, act, w, rw, pw, cw,
                                                       oscale, out);
}

// round 12
// speedup vs baseline: 1.1899x; 1.1899x over previous
#include <cuda_runtime.h>
#include <cstdint>

#define HDIM 2048
#define NTOK 8192          // B*S
#define NTHREADS 512
#define NCTAS 456          // 152 SMs * 3 resident CTAs
#define EPSV 1e-6f

__device__ __forceinline__ float4 ldcs4(const float* p) {
    float4 v;
    asm volatile("ld.global.cs.v4.f32 {%0,%1,%2,%3}, [%4];"
                 : "=f"(v.x), "=f"(v.y), "=f"(v.z), "=f"(v.w) : "l"(p));
    return v;
}
__device__ __forceinline__ void stcs4(float* p, float4 v) {
    asm volatile("st.global.cs.v4.f32 [%0], {%1,%2,%3,%4};"
                 :: "l"(p), "f"(v.x), "f"(v.y), "f"(v.z), "f"(v.w));
}
__device__ __forceinline__ float tanh_fast(float x) {
    float y; asm("tanh.approx.f32 %0, %1;" : "=f"(y) : "f"(x)); return y;
}
__device__ __forceinline__ float dot4(float4 a, float4 b) {
    return a.x*b.x + a.y*b.y + a.z*b.z + a.w*b.w;
}

__global__ __launch_bounds__(NTHREADS, 3)
void altup_v8_kernel(const float* __restrict__ hs,     // [4, NTOK, H]
                     const float* __restrict__ act,    // [NTOK, H]
                     const float* __restrict__ w,      // [H]
                     const float* __restrict__ rw,     // [4, H]
                     const float* __restrict__ pw,     // [16, 4]
                     const float* __restrict__ cw,     // [4, 4]
                     const float* __restrict__ oscale, // [H]
                     float* __restrict__ out)          // [4, NTOK, H]
{
    const int tid = threadIdx.x;
    const int h4  = tid * 4;
    const int warp = tid >> 5, lane = tid & 31;
    const float inv_h = 1.0f / (float)HDIM;

    __shared__ float q_s[4][HDIM];       // fused router weights w*rw[n]  (32 KB)
    __shared__ float red[2][16][10];     // ping-pong partial sums
    __shared__ float pw_s[64];
    __shared__ float cw_s[16];

    // ---- one-time staging: q = w * rw ----
    #pragma unroll
    for (int r = 0; r < 4; r++) {
        float4 wv = __ldg((const float4*)(w + h4));
        float4 rv = __ldg((const float4*)(rw + r*HDIM + h4));
        *(float4*)&q_s[r][h4] = make_float4(wv.x*rv.x, wv.y*rv.y, wv.z*rv.z, wv.w*rv.w);
    }
    if (tid < 64) pw_s[tid] = pw[tid];
    if (tid < 16) cw_s[tid] = cw[tid];
    const float4 sv = __ldg((const float4*)(oscale + h4));
    __syncthreads();

    int par = 0;
    for (int t = blockIdx.x; t < NTOK; t += NCTAS, par ^= 1) {
        // ---- phase 1: reduction streams ----
        float4 x0 = ldcs4(hs  + (size_t)t * HDIM + h4);
        float4 av = ldcs4(act + (size_t)t * HDIM + h4);

        float p[10];
        {
            float4 q0 = *(const float4*)&q_s[0][h4];
            float4 q1 = *(const float4*)&q_s[1][h4];
            p[0] = dot4(x0, x0);
            p[1] = dot4(x0, q0);  p[2] = dot4(x0, q1);
            p[5] = dot4(av, av);
            p[6] = dot4(av, q0);  p[7] = dot4(av, q1);
        }
        {
            float4 q2 = *(const float4*)&q_s[2][h4];
            float4 q3 = *(const float4*)&q_s[3][h4];
            p[3] = dot4(x0, q2);  p[4] = dot4(x0, q3);
            p[8] = dot4(av, q2);  p[9] = dot4(av, q3);
        }

        // ---- prefetch phase-2 streams before the reduce ----
        float4 x1 = ldcs4(hs + ((size_t)1*NTOK + t)*HDIM + h4);
        float4 x2 = ldcs4(hs + ((size_t)2*NTOK + t)*HDIM + h4);
        float4 x3 = ldcs4(hs + ((size_t)3*NTOK + t)*HDIM + h4);

        // ---- warp shuffle reduce, write partials, ONE barrier ----
        #pragma unroll
        for (int k = 0; k < 10; k++) {
            #pragma unroll
            for (int o = 16; o > 0; o >>= 1)
                p[k] += __shfl_xor_sync(0xffffffffu, p[k], o);
        }
        if (lane == 0) {
            #pragma unroll
            for (int k = 0; k < 10; k++) red[par][warp][k] = p[k];
        }
        __syncthreads();

        // ---- EVERY warp independently: finalize sums + coef math ----
        float f = 0.f;
        if (lane < 10) {
            #pragma unroll
            for (int wi = 0; wi < 16; wi++) f += red[par][wi][lane];
        }
        float fin[10];
        #pragma unroll
        for (int k = 0; k < 10; k++)
            fin[k] = __shfl_sync(0xffffffffu, f, k);

        float g0 = rsqrtf(fin[0] * inv_h + EPSV) * inv_h;
        float g1 = rsqrtf(fin[5] * inv_h + EPSV) * inv_h;

        // lanes 0..15: c[j][i] (lane = j*4+i); lanes 16..19: cc[lane-16]
        float cf;
        if (lane < 16) {
            float s = 0.f;
            #pragma unroll
            for (int n = 0; n < 4; n++)
                s = fmaf(tanh_fast(fin[1 + n] * g0), pw_s[lane*4 + n], s);
            cf = s;
        } else {
            int n = lane & 3;           // lanes 16..19 -> 0..3 (20..31 harmless)
            float s = 1.0f;
            #pragma unroll
            for (int k = 0; k < 4; k++)
                s = fmaf(tanh_fast(fin[6 + k] * g1), cw_s[n*4 + k], s);
            cf = s;
        }

        // ---- phase 2: elementwise combine, coefs via shuffles (5 live) ----
        float xc[4][4];
        xc[0][0]=x0.x; xc[0][1]=x0.y; xc[0][2]=x0.z; xc[0][3]=x0.w;
        xc[1][0]=x1.x; xc[1][1]=x1.y; xc[1][2]=x1.z; xc[1][3]=x1.w;
        xc[2][0]=x2.x; xc[2][1]=x2.y; xc[2][2]=x2.z; xc[2][3]=x2.w;
        xc[3][0]=x3.x; xc[3][1]=x3.y; xc[3][2]=x3.z; xc[3][3]=x3.w;
        const float ac[4] = {av.x, av.y, av.z, av.w};
        const float sc[4] = {sv.x, sv.y, sv.z, sv.w};

        float pr0[4], innov[4];
        {
            const float c0  = __shfl_sync(0xffffffffu, cf, 0);
            const float c1  = __shfl_sync(0xffffffffu, cf, 1);
            const float c2  = __shfl_sync(0xffffffffu, cf, 2);
            const float c3  = __shfl_sync(0xffffffffu, cf, 3);
            const float cc0 = __shfl_sync(0xffffffffu, cf, 16);
            float4 o4;
            float* op = &o4.x;
            #pragma unroll
            for (int comp = 0; comp < 4; comp++) {
                float s = xc[0][comp];
                s = fmaf(c0, xc[0][comp], s);
                s = fmaf(c1, xc[1][comp], s);
                s = fmaf(c2, xc[2][comp], s);
                s = fmaf(c3, xc[3][comp], s);
                pr0[comp] = s;
                innov[comp] = ac[comp] - s;
                op[comp] = (s + innov[comp]*cc0) * sc[comp];
            }
            stcs4(out + ((size_t)t)*HDIM + h4, o4);
        }
        #pragma unroll
        for (int j = 1; j < 4; j++) {
            const float c0  = __shfl_sync(0xffffffffu, cf, j*4 + 0);
            const float c1  = __shfl_sync(0xffffffffu, cf, j*4 + 1);
            const float c2  = __shfl_sync(0xffffffffu, cf, j*4 + 2);
            const float c3  = __shfl_sync(0xffffffffu, cf, j*4 + 3);
            const float ccj = __shfl_sync(0xffffffffu, cf, 16 + j);
            float4 o4;
            float* op = &o4.x;
            #pragma unroll
            for (int comp = 0; comp < 4; comp++) {
                float s = xc[j][comp];
                s = fmaf(c0, xc[0][comp], s);
                s = fmaf(c1, xc[1][comp], s);
                s = fmaf(c2, xc[2][comp], s);
                s = fmaf(c3, xc[3][comp], s);
                op[comp] = (s + innov[comp]*ccj) * sc[comp];
            }
            stcs4(out + ((size_t)j*NTOK + t)*HDIM + h4, o4);
        }
        // no trailing barrier: red ping-pongs by parity; a warp cannot reach
        // the same parity again without passing the (single) barrier of the
        // intervening iteration, which requires all warps to have consumed it.
    }
}

extern "C" void kernel_launch(void* const* d_in, const int* in_sizes, int n_in,
                              void* d_out, int out_size)
{
    const float* hs     = (const float*)d_in[0];
    const float* act    = (const float*)d_in[1];
    const float* w      = (const float*)d_in[2];
    const float* rw     = (const float*)d_in[3];
    const float* pw     = (const float*)d_in[4];
    const float* cw     = (const float*)d_in[5];
    const float* oscale = (const float*)d_in[6];
    float* out = (float*)d_out;

    altup_v8_kernel<<<NCTAS, NTHREADS>>>(hs, act, w, rw, pw, cw, oscale, out);
}